// round 3
// baseline (speedup 1.0000x reference)
#include <cuda_runtime.h>
#include <cuda_bf16.h>
#include <cstdint>

// Problem constants
#define BATCH   32
#define NN      64
#define DD      512
#define MM      2080          // N*(N+1)/2
#define TOPK    5
#define NEIGH   16
#define NEGK    16
#define TOTALS  85            // TOPK*(NEIGH+1)
#define KK      101           // NEGK + TOTALS
#define NSEG    65            // 2080/32 exact

// Radix sort config: 5-bit digits, 7 passes covers 32-bit key
#define RBITS   5
#define RBINS   32
#define RPASS   7
#define NSLOT   65            // (r,warp) slots, all full 32-lane
#define HSTR    66            // row stride in H (65 slots + total cell at [65])

// Output layout (concatenated float32): feat, pred_s_e, offset, score
#define FEAT_BASE 0
#define SE_BASE   (BATCH*KK*DD)
#define OFF_BASE  (SE_BASE + BATCH*KK*2)
#define SC_BASE   (OFF_BASE + BATCH*KK*2)

__device__ unsigned int g_rc[BATCH * KK];       // r*64+c per selected proposal

typedef unsigned int u32;
typedef unsigned short u16;

__device__ __forceinline__ u32 float_desc_key(float s) {
    u32 u = __float_as_uint(s);
    u32 k = (u & 0x80000000u) ? ~u : (u | 0x80000000u); // ascending map
    return ~k;                                          // descending
}

__device__ __forceinline__ u32 warp_incl_scan(u32 v, int lane) {
    #pragma unroll
    for (int o = 1; o < 32; o <<= 1) {
        u32 t = __shfl_up_sync(0xFFFFFFFFu, v, o);
        if (lane >= o) v += t;
    }
    return v;
}

__global__ void __launch_bounds__(1024, 1)
select_kernel(const float* __restrict__ score_pred,
              const float* __restrict__ offset_gt,
              const float* __restrict__ tmap,
              float* __restrict__ out)
{
    __shared__ u32 kA[MM], kB[MM];                  // 16640 B
    __shared__ u16 pA[MM], pB[MM];                  //  8320 B
    __shared__ u32 H[RBINS * HSTR];                 //  8448 B
    __shared__ u32 sh_base[RBINS];
    __shared__ u16 rc[MM];                          //  4160 B
    __shared__ u16 smom[MM];                        //  4160 B
    __shared__ u32 maskw[NSEG], supw[NSEG], selw[NSEG];
    __shared__ u16 unsup_idx[MM];                   //  4160 B
    __shared__ u16 sel_idx[TOTALS];
    __shared__ u32 upref[NSEG + 1], spref[NSEG + 1];

    const int b    = blockIdx.x;
    const int tid  = threadIdx.x;
    const int lane = tid & 31;
    const int warp = tid >> 5;
    const u32 lt   = (1u << lane) - 1u;

    // ---------------- Phase A: load scores, build keys ----------------
    for (int idx = tid; idx < NN * NN; idx += 1024) {
        int r = idx >> 6, c = idx & 63;
        if (c >= r) {
            int e = (r * (129 - r)) / 2 + (c - r);
            float s = score_pred[b * (NN * NN) + idx];
            kA[e] = float_desc_key(s);
            pA[e] = (u16)e;
            rc[e] = (u16)(r | (c << 8));
        }
    }
    __syncthreads();

    // ---------------- Phase B: stable LSD radix sort ----------------
    u32* sk = kA; u32* dk = kB;
    u16* sp = pA; u16* dp = pB;

    #pragma unroll
    for (int pass = 0; pass < RPASS; ++pass) {
        const int shift = pass * RBITS;

        // zero histogram
        for (int h = tid; h < RBINS * HSTR; h += 1024) H[h] = 0;
        __syncthreads();

        // histogram + within-slot rank. Element e = r*1024 + tid; slot = r*32 + warp.
        u32 key[3]; int dig[3], rk[3];
        #pragma unroll
        for (int r = 0; r < 3; ++r) {
            bool active = (r < 2) || (tid < 32);
            if (active) {
                int e = tid + r * 1024;
                key[r] = sk[e];
                dig[r] = (int)((key[r] >> shift) & (RBINS - 1));
                u32 m = __match_any_sync(0xFFFFFFFFu, dig[r]);
                rk[r] = __popc(m & lt);
                if (rk[r] == 0) H[dig[r] * HSTR + (r * 32 + warp)] = __popc(m);
            }
        }
        __syncthreads();

        // per-digit exclusive scan over 65 slots (warp d handles digit d)
        {
            int d = warp;                           // 32 warps == 32 digits
            u32 v0 = H[d * HSTR + lane];
            u32 v1 = H[d * HSTR + lane + 32];       // s = 32..63 (< 65)
            u32 v2 = (lane == 0) ? H[d * HSTR + 64] : 0;
            u32 s0 = warp_incl_scan(v0, lane);
            u32 t0 = __shfl_sync(0xFFFFFFFFu, s0, 31);
            u32 s1 = warp_incl_scan(v1, lane) + t0;
            u32 t1 = __shfl_sync(0xFFFFFFFFu, s1, 31);
            H[d * HSTR + lane]      = s0 - v0;      // exclusive
            H[d * HSTR + lane + 32] = s1 - v1;
            if (lane == 0) {
                H[d * HSTR + 64] = t1;              // exclusive for slot 64
                H[d * HSTR + 65] = t1 + v2;         // digit total
            }
        }
        __syncthreads();

        // cross-digit exclusive scan of totals
        if (warp == 0) {
            u32 T = H[lane * HSTR + 65];
            u32 s = warp_incl_scan(T, lane);
            sh_base[lane] = s - T;
        }
        __syncthreads();

        // stable scatter
        #pragma unroll
        for (int r = 0; r < 3; ++r) {
            bool active = (r < 2) || (tid < 32);
            if (active) {
                int e = tid + r * 1024;
                int pos = (int)(sh_base[dig[r]] + H[dig[r] * HSTR + (r * 32 + warp)]) + rk[r];
                dk[pos] = key[r];
                dp[pos] = sp[e];
            }
        }
        __syncthreads();

        // swap buffers
        u32* tk = sk; sk = dk; dk = tk;
        u16* tp = sp; sp = dp; dp = tp;
    }
    // RPASS=7 (odd): sorted result in kB/pB == sk/sp after final swap

    // ---------------- Phase C: sorted moments, init state ----------------
    for (int i = tid; i < MM; i += 1024) {
        u32 e = sp[i];
        u32 rcv = rc[e];
        int s = rcv & 0xFF;
        int en = (rcv >> 8) + 1;
        smom[i] = (u16)(s | (en << 8));
    }
    if (tid < NSEG) { supw[tid] = 0u; selw[tid] = 0u; }
    __syncthreads();

    // ---------------- Phase D: greedy NMS (replicated control) ----------------
    {
        int i = 0, cnt = 0;
        while (cnt < TOPK) {
            while (i < MM - 1 && ((supw[i >> 5] >> (i & 31)) & 1u)) ++i;
            if (i >= MM - 1) break;

            u32 mi = smom[i];
            int si = mi & 0xFF, ei = mi >> 8;

            #pragma unroll
            for (int rd = 0; rd < 3; ++rd) {
                int e2 = tid + rd * 1024;
                bool mk = false;
                if (e2 < MM) {
                    if (e2 == i) mk = true;
                    else if (e2 > i) {
                        u32 mmv = smom[e2];
                        int s3 = mmv & 0xFF, e3 = mmv >> 8;
                        int inter = min(e3, ei) - max(s3, si);
                        if (inter > 0) {
                            int uni = max(e3, ei) - min(s3, si);
                            mk = (2 * inter > uni);      // == (iou > 0.5) exactly
                        }
                    }
                }
                u32 bal = __ballot_sync(0xFFFFFFFFu, mk);
                int seg = warp + rd * 32;
                if (lane == 0 && seg < NSEG) maskw[seg] = bal;
            }
            __syncthreads();

            if (tid < NSEG) supw[tid] |= maskw[tid];     // single writer per word
            if (tid == 0) {
                int rem = NEIGH;
                int iseg = i >> 5;
                u32 ibit = 1u << (i & 31);
                for (int s2 = iseg; s2 < NSEG && rem > 0; ++s2) {
                    u32 w = maskw[s2];
                    if (s2 == iseg) w &= ~ibit;          // exclude e==i
                    if (!w) continue;
                    int pc = __popc(w);
                    if (pc <= rem) { selw[s2] |= w; rem -= pc; }
                    else {
                        u32 x = 0;
                        for (int q2 = 0; q2 < rem; ++q2) {
                            u32 lsb = w & (0u - w);
                            x |= lsb; w ^= lsb;
                        }
                        selw[s2] |= x;
                        rem = 0;
                    }
                }
                selw[iseg] |= ibit;
            }
            __syncthreads();
            ++i; ++cnt;
        }
        __syncthreads();   // uniform exit
    }

    // ---------------- Phase E: compactions ----------------
    if (tid == 0) {
        u32 runU = 0, runS = 0;
        #pragma unroll
        for (int s2 = 0; s2 < NSEG; ++s2) {
            upref[s2] = runU; runU += __popc(~supw[s2]);
            spref[s2] = runS; runS += __popc(selw[s2]);
        }
        upref[NSEG] = runU;           // n_unsup (NSEG*32 == MM exactly)
        spref[NSEG] = runS;           // n_sel
    }
    for (int t = tid; t < MM; t += 1024) unsup_idx[t] = (u16)(MM - 1);
    if (tid < TOTALS) sel_idx[tid] = (u16)(MM - 1);
    __syncthreads();

    for (int e2 = tid; e2 < MM; e2 += 1024) {
        int s2 = e2 >> 5;
        u32 bit = 1u << (e2 & 31);
        u32 low = bit - 1u;
        u32 uw = ~supw[s2];
        if (uw & bit) unsup_idx[upref[s2] + __popc(uw & low)] = (u16)e2;
        u32 sw = selw[s2];
        if (sw & bit) sel_idx[spref[s2] + __popc(sw & low)] = (u16)e2;
    }
    __syncthreads();

    // ---------------- Phase F: final index assembly + small outputs ----------------
    if (tid < KK) {
        int n_unsup = (int)upref[NSEG];
        int n_sel   = (int)spref[NSEG];
        int pad     = TOTALS - n_sel;

        int idxS;
        if (tid < NEGK) {
            int t = n_unsup - 1 - tid;
            if (t < 0) t = 0;
            if (t > MM - 1) t = MM - 1;
            idxS = unsup_idx[t];
        } else {
            int p = tid - NEGK;
            if (p < pad) idxS = unsup_idx[p];
            else {
                int q = p - pad;
                if (q > TOTALS - 1) q = TOTALS - 1;
                idxS = sel_idx[q];
            }
        }
        u32 orig = sp[idxS];                 // order[idx_sorted]
        u32 rcv  = rc[orig];
        int r = rcv & 0xFF;
        int c = rcv >> 8;

        int gk = b * KK + tid;
        g_rc[gk] = (u32)(r * NN + c);

        out[SE_BASE + gk * 2 + 0] = (float)r;
        out[SE_BASE + gk * 2 + 1] = (float)(c + 1);

        size_t oidx = ((size_t)(b * NN + r) * NN + c) * 2;
        out[OFF_BASE + gk * 2 + 0] = offset_gt[oidx + 0];
        out[OFF_BASE + gk * 2 + 1] = offset_gt[oidx + 1];

        out[SC_BASE + gk] = tmap[(size_t)(b * NN + r) * NN + c];
    }
}

// Flat feature gather: one float4 per thread, full occupancy.
// 3232 rows * 128 float4 = 413696 threads = 1616 CTAs * 256.
__global__ void __launch_bounds__(256)
gather_kernel(const float* __restrict__ map2d, float* __restrict__ out)
{
    int gid = blockIdx.x * 256 + threadIdx.x;
    int row = gid >> 7;            // row in [0, 3232)
    int q   = gid & 127;
    int b   = row / KK;
    const float4* __restrict__ src =
        (const float4*)(map2d + ((size_t)(b * (NN * NN)) + g_rc[row]) * DD);
    float4* __restrict__ dst = (float4*)(out + FEAT_BASE + (size_t)row * DD);
    dst[q] = src[q];
}

extern "C" void kernel_launch(void* const* d_in, const int* in_sizes, int n_in,
                              void* d_out, int out_size)
{
    const float* score_pred = (const float*)d_in[0];
    // d_in[1] = map2d_mask (deterministic triu — not needed)
    const float* map2d      = (const float*)d_in[2];
    const float* offset_gt  = (const float*)d_in[3];
    const float* tmap       = (const float*)d_in[4];
    float* out = (float*)d_out;

    select_kernel<<<BATCH, 1024>>>(score_pred, offset_gt, tmap, out);
    gather_kernel<<<(BATCH * KK * (DD / 4)) / 256, 256>>>(map2d, out);
}

// round 5
// speedup vs baseline: 1.4744x; 1.4744x over previous
#include <cuda_runtime.h>
#include <cuda_bf16.h>
#include <cstdint>

// Problem constants
#define BATCH   32
#define NN      64
#define DD      512
#define MM      2080          // N*(N+1)/2
#define SORTN   4096
#define TOPK    5
#define NEIGH   16
#define NEGK    16
#define TOTALS  85            // TOPK*(NEIGH+1)
#define KK      101           // NEGK + TOTALS
#define NSEG    65            // 2080/32 exact

// Output layout (concatenated float32): feat, pred_s_e, offset, score
#define FEAT_BASE 0
#define SE_BASE   (BATCH*KK*DD)
#define OFF_BASE  (SE_BASE + BATCH*KK*2)
#define SC_BASE   (OFF_BASE + BATCH*KK*2)

typedef unsigned long long u64;
typedef unsigned int u32;
typedef unsigned short u16;

__device__ __forceinline__ u32 float_desc_key(float s) {
    u32 u = __float_as_uint(s);
    u32 k = (u & 0x80000000u) ? ~u : (u | 0x80000000u); // ascending map
    return ~k;                                          // descending
}

__device__ __forceinline__ u64 u64min(u64 a, u64 b) { return a < b ? a : b; }
__device__ __forceinline__ u64 u64max(u64 a, u64 b) { return a > b ? a : b; }

__device__ __forceinline__ void cswap(u64 &a, u64 &b, bool up) {
    if ((a > b) == up) { u64 t = a; a = b; b = t; }
}

__device__ __forceinline__ u32 warp_incl_scan(u32 v, int lane) {
    #pragma unroll
    for (int o = 1; o < 32; o <<= 1) {
        u32 t = __shfl_up_sync(0xFFFFFFFFu, v, o);
        if (lane >= o) v += t;
    }
    return v;
}

// Register/warp-local bitonic stages for j = jstart down to 1 (jstart <= 64).
// Element of K[q] has global index ebase + q*32 (ebase = warp*128 + lane).
__device__ __forceinline__ void reg_phase(u64 K[4], int k, int jstart, int ebase) {
    int j = jstart;
    if (j >= 64) {                                  // j=64: (K0,K2),(K1,K3)
        #pragma unroll
        for (int q = 0; q < 2; ++q) {
            bool up = (((ebase + q * 32) & k) == 0);
            cswap(K[q], K[q + 2], up);
        }
        j = 32;
    }
    if (j >= 32) {                                  // j=32: (K0,K1),(K2,K3)
        #pragma unroll
        for (int q = 0; q < 4; q += 2) {
            bool up = (((ebase + q * 32) & k) == 0);
            cswap(K[q], K[q + 1], up);
        }
        j = 16;
    }
    for (; j >= 1; j >>= 1) {                       // shuffle stages
        #pragma unroll
        for (int q = 0; q < 4; ++q) {
            int e = ebase + q * 32;
            bool up = ((e & k) == 0);
            u64 o = __shfl_xor_sync(0xFFFFFFFFu, K[q], j);
            bool upper = (e & j) != 0;              // == lane&j (j<=16)
            K[q] = (up != upper) ? u64min(K[q], o) : u64max(K[q], o);
        }
    }
}

__global__ void __launch_bounds__(1024, 1)
fused_kernel(const float* __restrict__ score_pred,
             const float* __restrict__ map2d,
             const float* __restrict__ offset_gt,
             const float* __restrict__ tmap,
             float* __restrict__ out)
{
    __shared__ u64 skeys[SORTN];                    // 32768 B
    __shared__ u16 rc[MM];                          // r | c<<8 (original order)
    __shared__ u16 smom[MM];                        // s | e<<8 (sorted order)
    __shared__ u32 maskw[NSEG], supw[NSEG], selw[NSEG];
    __shared__ u32 nbpref[NSEG];
    __shared__ u16 unsup_idx[MM];
    __shared__ u16 sel_idx[TOTALS];
    __shared__ u32 upref[NSEG + 1], spref[NSEG + 1];
    __shared__ u32 s_sel[KK];                       // r*64+c of final picks

    const int b    = blockIdx.x;
    const int tid  = threadIdx.x;
    const int lane = tid & 31;
    const int warp = tid >> 5;
    const int ebase = warp * 128 + lane;

    // ---------------- Phase A: build keys (scatter by (r,c)) ----------------
    for (int idx = tid; idx < SORTN; idx += 1024) skeys[idx] = ~0ULL;
    __syncthreads();
    for (int idx = tid; idx < NN * NN; idx += 1024) {
        int r = idx >> 6, c = idx & 63;
        if (c >= r) {
            int e = (r * (129 - r)) / 2 + (c - r);
            float s = score_pred[b * (NN * NN) + idx];
            skeys[e] = ((u64)float_desc_key(s) << 32) | (u32)e;
            rc[e] = (u16)(r | (c << 8));
        }
    }
    __syncthreads();

    // ---------------- Phase B: register-blocked hybrid bitonic sort ----------------
    u64 K[4];
    #pragma unroll
    for (int q = 0; q < 4; ++q) K[q] = skeys[warp * 128 + q * 32 + lane];

    for (int k = 2; k <= 128; k <<= 1) reg_phase(K, k, k >> 1, ebase);

    for (int k = 256; k <= SORTN; k <<= 1) {
        #pragma unroll
        for (int q = 0; q < 4; ++q) skeys[warp * 128 + q * 32 + lane] = K[q];
        __syncthreads();
        for (int j = k >> 1; j >= 128; j >>= 1) {
            #pragma unroll
            for (int t2i = 0; t2i < 2; ++t2i) {
                int t2 = tid + t2i * 1024;
                int i = ((t2 & ~(j - 1)) << 1) | (t2 & (j - 1));
                int p = i | j;
                bool up = ((i & k) == 0);
                u64 a = skeys[i], bb = skeys[p];
                if ((a > bb) == up) { skeys[i] = bb; skeys[p] = a; }
            }
            __syncthreads();
        }
        #pragma unroll
        for (int q = 0; q < 4; ++q) K[q] = skeys[warp * 128 + q * 32 + lane];
        reg_phase(K, k, 64, ebase);
    }
    #pragma unroll
    for (int q = 0; q < 4; ++q) skeys[warp * 128 + q * 32 + lane] = K[q];
    __syncthreads();

    // ---------------- Phase C: sorted moments, init state ----------------
    for (int i = tid; i < MM; i += 1024) {
        u32 e = (u32)skeys[i];
        u32 rcv = rc[e];
        int s = rcv & 0xFF;
        int en = (rcv >> 8) + 1;
        smom[i] = (u16)(s | (en << 8));
    }
    if (tid < NSEG) { supw[tid] = 0u; selw[tid] = 0u; }
    __syncthreads();

    // ---------------- Phase D: greedy NMS ----------------
    {
        int i = 0, cnt = 0;
        while (cnt < TOPK) {
            // word-skip scan for next free index >= i (replicated, broadcast reads)
            {
                int s2 = i >> 5;
                u32 w = (~supw[s2]) & (0xFFFFFFFFu << (i & 31));
                while (w == 0 && s2 < NSEG - 1) { ++s2; w = ~supw[s2]; }
                i = w ? (s2 * 32 + __ffs(w) - 1) : MM;
            }
            if (i >= MM - 1) break;

            const int iseg = i >> 5;
            const u32 ibit = 1u << (i & 31);
            u32 mi = smom[i];
            int si = mi & 0xFF, ei = mi >> 8;

            // ballot IoU masks (mask includes bit i itself)
            #pragma unroll
            for (int rd = 0; rd < 3; ++rd) {
                int e2 = tid + rd * 1024;
                bool mk = false;
                if (e2 < MM) {
                    if (e2 == i) mk = true;
                    else if (e2 > i) {
                        u32 mmv = smom[e2];
                        int s3 = mmv & 0xFF, e3 = mmv >> 8;
                        int inter = min(e3, ei) - max(s3, si);
                        if (inter > 0) {
                            int uni = max(e3, ei) - min(s3, si);
                            mk = (2 * inter > uni);      // == (iou > 0.5) exactly
                        }
                    }
                }
                u32 bal = __ballot_sync(0xFFFFFFFFu, mk);
                int seg = warp + rd * 32;
                if (lane == 0 && seg < NSEG) maskw[seg] = bal;
            }
            __syncthreads();

            // warp0: exclusive prefix of masked-neighbor counts over 65 segments
            if (warp == 0) {
                u32 m0 = maskw[lane];
                if (lane == iseg) m0 &= ~ibit;
                u32 m1 = maskw[lane + 32];
                if (lane + 32 == iseg) m1 &= ~ibit;
                u32 v0 = __popc(m0), v1 = __popc(m1);
                u32 s0 = warp_incl_scan(v0, lane);
                u32 t0 = __shfl_sync(0xFFFFFFFFu, s0, 31);
                u32 s1 = warp_incl_scan(v1, lane) + t0;
                u32 t1 = __shfl_sync(0xFFFFFFFFu, s1, 31);
                nbpref[lane]      = s0 - v0;
                nbpref[lane + 32] = s1 - v1;
                if (lane == 0) nbpref[64] = t1;
            }
            // warps 1-3: suppression update over ALL 65 segments (incl. seg 64)
            if (warp >= 1 && warp <= 3) {
                int s2 = tid - 32;                 // 0..95
                if (s2 < NSEG) supw[s2] |= maskw[s2];
            }
            __syncthreads();

            // selection update: lowest (NEIGH - pref) masked bits per segment + pick bit
            if (tid < NSEG) {
                u32 w = maskw[tid];
                if (tid == iseg) w &= ~ibit;
                int rem = NEIGH - (int)nbpref[tid];
                u32 add = 0;
                if (rem > 0) {
                    if (__popc(w) <= rem) add = w;
                    else {
                        u32 x = w;
                        #pragma unroll
                        for (int q2 = 0; q2 < NEIGH; ++q2)
                            if (q2 < rem) x &= (x - 1);   // clear rem lowest bits
                        add = w ^ x;                       // lowest rem set bits
                    }
                }
                if (tid == iseg) add |= ibit;
                selw[tid] |= add;
            }
            __syncthreads();
            ++i; ++cnt;
        }
        __syncthreads();   // uniform exit
    }

    // ---------------- Phase E: parallel compactions ----------------
    if (warp == 0) {       // unsup prefix
        u32 v0 = __popc(~supw[lane]);
        u32 v1 = __popc(~supw[lane + 32]);
        u32 v2 = (lane == 0) ? __popc(~supw[64]) : 0;
        u32 s0 = warp_incl_scan(v0, lane);
        u32 t0 = __shfl_sync(0xFFFFFFFFu, s0, 31);
        u32 s1 = warp_incl_scan(v1, lane) + t0;
        u32 t1 = __shfl_sync(0xFFFFFFFFu, s1, 31);
        upref[lane]      = s0 - v0;
        upref[lane + 32] = s1 - v1;
        if (lane == 0) { upref[64] = t1; upref[65] = t1 + v2; }
    }
    if (warp == 1) {       // sel prefix
        u32 v0 = __popc(selw[lane]);
        u32 v1 = __popc(selw[lane + 32]);
        u32 v2 = (lane == 0) ? __popc(selw[64]) : 0;
        u32 s0 = warp_incl_scan(v0, lane);
        u32 t0 = __shfl_sync(0xFFFFFFFFu, s0, 31);
        u32 s1 = warp_incl_scan(v1, lane) + t0;
        u32 t1 = __shfl_sync(0xFFFFFFFFu, s1, 31);
        spref[lane]      = s0 - v0;
        spref[lane + 32] = s1 - v1;
        if (lane == 0) { spref[64] = t1; spref[65] = t1 + v2; }
    }
    for (int t = tid; t < MM; t += 1024) unsup_idx[t] = (u16)(MM - 1);
    if (tid >= 1024 - TOTALS) sel_idx[tid - (1024 - TOTALS)] = (u16)(MM - 1);
    __syncthreads();

    for (int e2 = tid; e2 < MM; e2 += 1024) {
        int s2 = e2 >> 5;
        u32 bit = 1u << (e2 & 31);
        u32 low = bit - 1u;
        u32 uw = ~supw[s2];
        if (uw & bit) unsup_idx[upref[s2] + __popc(uw & low)] = (u16)e2;
        u32 sw = selw[s2];
        if (sw & bit) sel_idx[spref[s2] + __popc(sw & low)] = (u16)e2;
    }
    __syncthreads();

    // ---------------- Phase F: final index assembly + small outputs ----------------
    if (tid < KK) {
        int n_unsup = (int)upref[NSEG];
        int n_sel   = (int)spref[NSEG];
        int pad     = TOTALS - n_sel;

        int idxS;
        if (tid < NEGK) {
            int t = n_unsup - 1 - tid;
            if (t < 0) t = 0;
            if (t > MM - 1) t = MM - 1;
            idxS = unsup_idx[t];
        } else {
            int p = tid - NEGK;
            if (p < pad) idxS = unsup_idx[p];
            else {
                int q = p - pad;
                if (q > TOTALS - 1) q = TOTALS - 1;
                idxS = sel_idx[q];
            }
        }
        u32 orig = (u32)skeys[idxS];         // order[idx_sorted]
        u32 rcv  = rc[orig];
        int r = rcv & 0xFF;
        int c = rcv >> 8;

        int gk = b * KK + tid;
        s_sel[tid] = (u32)(r * NN + c);

        out[SE_BASE + gk * 2 + 0] = (float)r;
        out[SE_BASE + gk * 2 + 1] = (float)(c + 1);

        size_t oidx = ((size_t)(b * NN + r) * NN + c) * 2;
        out[OFF_BASE + gk * 2 + 0] = offset_gt[oidx + 0];
        out[OFF_BASE + gk * 2 + 1] = offset_gt[oidx + 1];

        out[SC_BASE + gk] = tmap[(size_t)(b * NN + r) * NN + c];
    }
    __syncthreads();

    // ---------------- Phase G: fused feature gather (101 rows x 2KB) ----------------
    {
        const float4* __restrict__ src4 = (const float4*)map2d;
        float4* __restrict__ dst4 = (float4*)(out + FEAT_BASE);
        const size_t bbase = (size_t)b * (NN * NN) * (DD / 4);
        const size_t obase = (size_t)b * KK * (DD / 4);
        #pragma unroll 2
        for (int t = tid; t < KK * (DD / 4); t += 1024) {
            int row = t >> 7;                 // /128 float4 per row
            int q   = t & 127;
            dst4[obase + (size_t)row * (DD / 4) + q] =
                src4[bbase + (size_t)s_sel[row] * (DD / 4) + q];
        }
    }
}

extern "C" void kernel_launch(void* const* d_in, const int* in_sizes, int n_in,
                              void* d_out, int out_size)
{
    const float* score_pred = (const float*)d_in[0];
    // d_in[1] = map2d_mask (deterministic triu — not needed)
    const float* map2d      = (const float*)d_in[2];
    const float* offset_gt  = (const float*)d_in[3];
    const float* tmap       = (const float*)d_in[4];
    float* out = (float*)d_out;

    fused_kernel<<<BATCH, 1024>>>(score_pred, map2d, offset_gt, tmap, out);
}

// round 6
// speedup vs baseline: 1.5460x; 1.0486x over previous
#include <cuda_runtime.h>
#include <cuda_bf16.h>
#include <cstdint>

// Problem constants
#define BATCH   32
#define NN      64
#define DD      512
#define MM      2080          // N*(N+1)/2
#define SORTN   4096
#define TOPK    5
#define NEIGH   16
#define NEGK    16
#define TOTALS  85            // TOPK*(NEIGH+1)
#define KK      101           // NEGK + TOTALS
#define NSEG    65            // 2080/32 exact

// Output layout (concatenated float32): feat, pred_s_e, offset, score
#define FEAT_BASE 0
#define SE_BASE   (BATCH*KK*DD)
#define OFF_BASE  (SE_BASE + BATCH*KK*2)
#define SC_BASE   (OFF_BASE + BATCH*KK*2)

typedef unsigned long long u64;
typedef unsigned int u32;
typedef unsigned short u16;

__device__ __forceinline__ u32 float_desc_key(float s) {
    u32 u = __float_as_uint(s);
    u32 k = (u & 0x80000000u) ? ~u : (u | 0x80000000u); // ascending map
    return ~k;                                          // descending
}

__device__ __forceinline__ u64 u64min(u64 a, u64 b) { return a < b ? a : b; }
__device__ __forceinline__ u64 u64max(u64 a, u64 b) { return a > b ? a : b; }

__device__ __forceinline__ void cswap(u64 &a, u64 &b, bool up) {
    if ((a > b) == up) { u64 t = a; a = b; b = t; }
}

__device__ __forceinline__ u32 warp_incl_scan(u32 v, int lane) {
    #pragma unroll
    for (int o = 1; o < 32; o <<= 1) {
        u32 t = __shfl_up_sync(0xFFFFFFFFu, v, o);
        if (lane >= o) v += t;
    }
    return v;
}

// Register/warp-local bitonic stages for j = jstart down to 1 (jstart <= 64).
// Element of K[q] has global index ebase + q*32 (ebase = warp*128 + lane).
__device__ __forceinline__ void reg_phase(u64 K[4], int k, int jstart, int ebase) {
    int j = jstart;
    if (j >= 64) {                                  // j=64: (K0,K2),(K1,K3)
        #pragma unroll
        for (int q = 0; q < 2; ++q) {
            bool up = (((ebase + q * 32) & k) == 0);
            cswap(K[q], K[q + 2], up);
        }
        j = 32;
    }
    if (j >= 32) {                                  // j=32: (K0,K1),(K2,K3)
        #pragma unroll
        for (int q = 0; q < 4; q += 2) {
            bool up = (((ebase + q * 32) & k) == 0);
            cswap(K[q], K[q + 1], up);
        }
        j = 16;
    }
    for (; j >= 1; j >>= 1) {                       // shuffle stages
        #pragma unroll
        for (int q = 0; q < 4; ++q) {
            int e = ebase + q * 32;
            bool up = ((e & k) == 0);
            u64 o = __shfl_xor_sync(0xFFFFFFFFu, K[q], j);
            bool upper = (e & j) != 0;              // == lane&j (j<=16)
            K[q] = (up != upper) ? u64min(K[q], o) : u64max(K[q], o);
        }
    }
}

__global__ void __launch_bounds__(1024, 1)
fused_kernel(const float* __restrict__ score_pred,
             const float* __restrict__ map2d,
             const float* __restrict__ offset_gt,
             const float* __restrict__ tmap,
             float* __restrict__ out)
{
    __shared__ u64 skeys[SORTN];                    // 32768 B
    __shared__ u16 rc[MM];                          // r | c<<8 (original order)
    __shared__ u16 smom[MM];                        // s | e<<8 (sorted order)
    __shared__ u32 maskw[NSEG], supw[NSEG], selw[NSEG];
    __shared__ u32 nbpref[NSEG];
    __shared__ u16 unsup_idx[MM];
    __shared__ u16 sel_idx[TOTALS];
    __shared__ u32 upref[NSEG + 1], spref[NSEG + 1];
    __shared__ u32 s_sel[KK];                       // r*64+c of final picks

    const int b    = blockIdx.x;
    const int tid  = threadIdx.x;
    const int lane = tid & 31;
    const int warp = tid >> 5;
    const int ebase = warp * 128 + lane;

    // ---------------- Phase A: build keys (scatter by (r,c)) ----------------
    for (int idx = tid; idx < SORTN; idx += 1024) skeys[idx] = ~0ULL;
    __syncthreads();
    for (int idx = tid; idx < NN * NN; idx += 1024) {
        int r = idx >> 6, c = idx & 63;
        if (c >= r) {
            int e = (r * (129 - r)) / 2 + (c - r);
            float s = score_pred[b * (NN * NN) + idx];
            skeys[e] = ((u64)float_desc_key(s) << 32) | (u32)e;
            rc[e] = (u16)(r | (c << 8));
        }
    }
    __syncthreads();

    // ---------------- Phase B: hybrid bitonic sort with fused smem passes ----------------
    u64 K[4];
    #pragma unroll
    for (int q = 0; q < 4; ++q) K[q] = skeys[warp * 128 + q * 32 + lane];

    for (int k = 2; k <= 128; k <<= 1) reg_phase(K, k, k >> 1, ebase);

    for (int k = 256; k <= SORTN; k <<= 1) {
        #pragma unroll
        for (int q = 0; q < 4; ++q) skeys[warp * 128 + q * 32 + lane] = K[q];
        __syncthreads();

        int j = k >> 1;
        // fused passes: two levels (j, j/2) per smem round-trip, j/2 >= 128
        while (j >= 256) {
            int j2 = j >> 1;
            int base = ((tid & ~(j2 - 1)) << 2) | (tid & (j2 - 1));
            bool up = ((base & k) == 0);
            u64 a0 = skeys[base];
            u64 a1 = skeys[base + j2];
            u64 a2 = skeys[base + j];
            u64 a3 = skeys[base + j + j2];
            cswap(a0, a2, up); cswap(a1, a3, up);   // level j
            cswap(a0, a1, up); cswap(a2, a3, up);   // level j/2
            skeys[base]          = a0;
            skeys[base + j2]     = a1;
            skeys[base + j]      = a2;
            skeys[base + j + j2] = a3;
            __syncthreads();
            j >>= 2;
        }
        // possible leftover single level j == 128
        if (j == 128) {
            #pragma unroll
            for (int t2i = 0; t2i < 2; ++t2i) {
                int t2 = tid + t2i * 1024;
                int i = ((t2 & ~127) << 1) | (t2 & 127);
                int p = i | 128;
                bool up = ((i & k) == 0);
                u64 a = skeys[i], bb = skeys[p];
                if ((a > bb) == up) { skeys[i] = bb; skeys[p] = a; }
            }
            __syncthreads();
        }
        #pragma unroll
        for (int q = 0; q < 4; ++q) K[q] = skeys[warp * 128 + q * 32 + lane];
        reg_phase(K, k, 64, ebase);
    }
    #pragma unroll
    for (int q = 0; q < 4; ++q) skeys[warp * 128 + q * 32 + lane] = K[q];
    __syncthreads();

    // ---------------- Phase C: sorted moments (regs + smem), init state ----------------
    u32 mreg[3];                                    // this thread's smom values
    #pragma unroll
    for (int rd = 0; rd < 3; ++rd) {
        int i = tid + rd * 1024;
        u32 v = 0;
        if (i < MM) {
            u32 e = (u32)skeys[i];
            u32 rcv = rc[e];
            int s = rcv & 0xFF;
            int en = (rcv >> 8) + 1;
            v = (u32)(s | (en << 8));
            smom[i] = (u16)v;
        }
        mreg[rd] = v;
    }
    if (tid < NSEG) { supw[tid] = 0u; selw[tid] = 0u; }
    __syncthreads();

    // ---------------- Phase D: greedy NMS ----------------
    {
        int i = 0, cnt = 0;
        while (cnt < TOPK) {
            // word-skip scan for next free index >= i (replicated, broadcast reads)
            {
                int s2 = i >> 5;
                u32 w = (~supw[s2]) & (0xFFFFFFFFu << (i & 31));
                while (w == 0 && s2 < NSEG - 1) { ++s2; w = ~supw[s2]; }
                i = w ? (s2 * 32 + __ffs(w) - 1) : MM;
            }
            if (i >= MM - 1) break;

            const int iseg = i >> 5;
            const u32 ibit = 1u << (i & 31);
            u32 mi = smom[i];                       // single broadcast LDS
            int si = mi & 0xFF, ei = mi >> 8;

            // ballot IoU masks from register moments (mask includes bit i)
            #pragma unroll
            for (int rd = 0; rd < 3; ++rd) {
                int e2 = tid + rd * 1024;
                bool mk = false;
                if (e2 < MM) {
                    if (e2 == i) mk = true;
                    else if (e2 > i) {
                        u32 mmv = mreg[rd];
                        int s3 = mmv & 0xFF, e3 = mmv >> 8;
                        int inter = min(e3, ei) - max(s3, si);
                        if (inter > 0) {
                            int uni = max(e3, ei) - min(s3, si);
                            mk = (2 * inter > uni);      // == (iou > 0.5) exactly
                        }
                    }
                }
                u32 bal = __ballot_sync(0xFFFFFFFFu, mk);
                int seg = warp + rd * 32;
                if (lane == 0 && seg < NSEG) maskw[seg] = bal;
            }
            __syncthreads();

            // warp0: exclusive prefix of masked-neighbor counts over 65 segments
            if (warp == 0) {
                u32 m0 = maskw[lane];
                if (lane == iseg) m0 &= ~ibit;
                u32 m1 = maskw[lane + 32];
                if (lane + 32 == iseg) m1 &= ~ibit;
                u32 v0 = __popc(m0), v1 = __popc(m1);
                u32 s0 = warp_incl_scan(v0, lane);
                u32 t0 = __shfl_sync(0xFFFFFFFFu, s0, 31);
                u32 s1 = warp_incl_scan(v1, lane) + t0;
                u32 t1 = __shfl_sync(0xFFFFFFFFu, s1, 31);
                nbpref[lane]      = s0 - v0;
                nbpref[lane + 32] = s1 - v1;
                if (lane == 0) nbpref[64] = t1;
            }
            // warps 1-3: suppression update over ALL 65 segments (incl. seg 64)
            if (warp >= 1 && warp <= 3) {
                int s2 = tid - 32;                 // 0..95
                if (s2 < NSEG) supw[s2] |= maskw[s2];
            }
            __syncthreads();

            // selection update: lowest (NEIGH - pref) masked bits per segment + pick bit
            if (tid < NSEG) {
                u32 w = maskw[tid];
                if (tid == iseg) w &= ~ibit;
                int rem = NEIGH - (int)nbpref[tid];
                u32 add = 0;
                if (rem > 0) {
                    if (__popc(w) <= rem) add = w;
                    else {
                        u32 x = w;
                        #pragma unroll
                        for (int q2 = 0; q2 < NEIGH; ++q2)
                            if (q2 < rem) x &= (x - 1);   // clear rem lowest bits
                        add = w ^ x;                       // lowest rem set bits
                    }
                }
                if (tid == iseg) add |= ibit;
                selw[tid] |= add;
            }
            __syncthreads();
            ++i; ++cnt;
        }
        __syncthreads();   // uniform exit
    }

    // ---------------- Phase E: parallel compactions ----------------
    if (warp == 0) {       // unsup prefix
        u32 v0 = __popc(~supw[lane]);
        u32 v1 = __popc(~supw[lane + 32]);
        u32 v2 = (lane == 0) ? __popc(~supw[64]) : 0;
        u32 s0 = warp_incl_scan(v0, lane);
        u32 t0 = __shfl_sync(0xFFFFFFFFu, s0, 31);
        u32 s1 = warp_incl_scan(v1, lane) + t0;
        u32 t1 = __shfl_sync(0xFFFFFFFFu, s1, 31);
        upref[lane]      = s0 - v0;
        upref[lane + 32] = s1 - v1;
        if (lane == 0) { upref[64] = t1; upref[65] = t1 + v2; }
    }
    if (warp == 1) {       // sel prefix
        u32 v0 = __popc(selw[lane]);
        u32 v1 = __popc(selw[lane + 32]);
        u32 v2 = (lane == 0) ? __popc(selw[64]) : 0;
        u32 s0 = warp_incl_scan(v0, lane);
        u32 t0 = __shfl_sync(0xFFFFFFFFu, s0, 31);
        u32 s1 = warp_incl_scan(v1, lane) + t0;
        u32 t1 = __shfl_sync(0xFFFFFFFFu, s1, 31);
        spref[lane]      = s0 - v0;
        spref[lane + 32] = s1 - v1;
        if (lane == 0) { spref[64] = t1; spref[65] = t1 + v2; }
    }
    for (int t = tid; t < MM; t += 1024) unsup_idx[t] = (u16)(MM - 1);
    if (tid >= 1024 - TOTALS) sel_idx[tid - (1024 - TOTALS)] = (u16)(MM - 1);
    __syncthreads();

    for (int e2 = tid; e2 < MM; e2 += 1024) {
        int s2 = e2 >> 5;
        u32 bit = 1u << (e2 & 31);
        u32 low = bit - 1u;
        u32 uw = ~supw[s2];
        if (uw & bit) unsup_idx[upref[s2] + __popc(uw & low)] = (u16)e2;
        u32 sw = selw[s2];
        if (sw & bit) sel_idx[spref[s2] + __popc(sw & low)] = (u16)e2;
    }
    __syncthreads();

    // ---------------- Phase F: final index assembly + small outputs ----------------
    if (tid < KK) {
        int n_unsup = (int)upref[NSEG];
        int n_sel   = (int)spref[NSEG];
        int pad     = TOTALS - n_sel;

        int idxS;
        if (tid < NEGK) {
            int t = n_unsup - 1 - tid;
            if (t < 0) t = 0;
            if (t > MM - 1) t = MM - 1;
            idxS = unsup_idx[t];
        } else {
            int p = tid - NEGK;
            if (p < pad) idxS = unsup_idx[p];
            else {
                int q = p - pad;
                if (q > TOTALS - 1) q = TOTALS - 1;
                idxS = sel_idx[q];
            }
        }
        u32 orig = (u32)skeys[idxS];         // order[idx_sorted]
        u32 rcv  = rc[orig];
        int r = rcv & 0xFF;
        int c = rcv >> 8;

        int gk = b * KK + tid;
        s_sel[tid] = (u32)(r * NN + c);

        out[SE_BASE + gk * 2 + 0] = (float)r;
        out[SE_BASE + gk * 2 + 1] = (float)(c + 1);

        size_t oidx = ((size_t)(b * NN + r) * NN + c) * 2;
        out[OFF_BASE + gk * 2 + 0] = offset_gt[oidx + 0];
        out[OFF_BASE + gk * 2 + 1] = offset_gt[oidx + 1];

        out[SC_BASE + gk] = tmap[(size_t)(b * NN + r) * NN + c];
    }
    __syncthreads();

    // ---------------- Phase G: fused feature gather (101 rows x 2KB) ----------------
    {
        const float4* __restrict__ src4 = (const float4*)map2d;
        float4* __restrict__ dst4 = (float4*)(out + FEAT_BASE);
        const size_t bbase = (size_t)b * (NN * NN) * (DD / 4);
        const size_t obase = (size_t)b * KK * (DD / 4);
        #pragma unroll 4
        for (int t = tid; t < KK * (DD / 4); t += 1024) {
            int row = t >> 7;                 // /128 float4 per row
            int q   = t & 127;
            dst4[obase + (size_t)row * (DD / 4) + q] =
                src4[bbase + (size_t)s_sel[row] * (DD / 4) + q];
        }
    }
}

extern "C" void kernel_launch(void* const* d_in, const int* in_sizes, int n_in,
                              void* d_out, int out_size)
{
    const float* score_pred = (const float*)d_in[0];
    // d_in[1] = map2d_mask (deterministic triu — not needed)
    const float* map2d      = (const float*)d_in[2];
    const float* offset_gt  = (const float*)d_in[3];
    const float* tmap       = (const float*)d_in[4];
    float* out = (float*)d_out;

    fused_kernel<<<BATCH, 1024>>>(score_pred, map2d, offset_gt, tmap, out);
}

// round 7
// speedup vs baseline: 1.5539x; 1.0051x over previous
#include <cuda_runtime.h>
#include <cuda_bf16.h>
#include <cstdint>

// Problem constants
#define BATCH   32
#define NN      64
#define DD      512
#define MM      2080          // N*(N+1)/2
#define SORTN   4096
#define NTHR    512
#define TOPK    5
#define NEIGH   16
#define NEGK    16
#define TOTALS  85            // TOPK*(NEIGH+1)
#define KK      101           // NEGK + TOTALS
#define NSEG    65            // 2080/32 exact

// Output layout (concatenated float32): feat, pred_s_e, offset, score
#define FEAT_BASE 0
#define SE_BASE   (BATCH*KK*DD)
#define OFF_BASE  (SE_BASE + BATCH*KK*2)
#define SC_BASE   (OFF_BASE + BATCH*KK*2)

typedef unsigned long long u64;
typedef unsigned int u32;
typedef unsigned short u16;

__device__ __forceinline__ u32 float_desc_key(float s) {
    u32 u = __float_as_uint(s);
    u32 k = (u & 0x80000000u) ? ~u : (u | 0x80000000u); // ascending map
    return ~k;                                          // descending
}

__device__ __forceinline__ u64 u64min(u64 a, u64 b) { return a < b ? a : b; }
__device__ __forceinline__ u64 u64max(u64 a, u64 b) { return a > b ? a : b; }

__device__ __forceinline__ void cswap(u64 &a, u64 &b, bool up) {
    if ((a > b) == up) { u64 t = a; a = b; b = t; }
}

__device__ __forceinline__ u32 warp_incl_scan(u32 v, int lane) {
    #pragma unroll
    for (int o = 1; o < 32; o <<= 1) {
        u32 t = __shfl_up_sync(0xFFFFFFFFu, v, o);
        if (lane >= o) v += t;
    }
    return v;
}

// lowest `rem` set bits of w (rem may exceed popc -> whole w)
__device__ __forceinline__ u32 low_bits(u32 w, int rem) {
    if (rem <= 0) return 0;
    if (__popc(w) <= rem) return w;
    u32 x = w;
    #pragma unroll
    for (int q = 0; q < NEIGH; ++q)
        if (q < rem) x &= (x - 1);
    return w ^ x;
}

// Warp-local bitonic stages, 8 elements per thread (warp spans 256 elements).
// K[q] holds element ebase + q*32, ebase = warp*256 + lane. jstart <= 128.
__device__ __forceinline__ void reg_phase8(u64 K[8], int k, int jstart, int ebase) {
    int j = jstart;
    if (j >= 128) {                                 // (q, q+4)
        #pragma unroll
        for (int q = 0; q < 4; ++q) {
            bool up = (((ebase + q * 32) & k) == 0);
            cswap(K[q], K[q + 4], up);
        }
        j = 64;
    }
    if (j >= 64) {                                  // (0,2)(1,3)(4,6)(5,7)
        #pragma unroll
        for (int h = 0; h < 8; h += 4)
            #pragma unroll
            for (int q = 0; q < 2; ++q) {
                bool up = (((ebase + (h + q) * 32) & k) == 0);
                cswap(K[h + q], K[h + q + 2], up);
            }
        j = 32;
    }
    if (j >= 32) {                                  // (q, q+1) pairs
        #pragma unroll
        for (int q = 0; q < 8; q += 2) {
            bool up = (((ebase + q * 32) & k) == 0);
            cswap(K[q], K[q + 1], up);
        }
        j = 16;
    }
    for (; j >= 1; j >>= 1) {                       // shuffle stages
        #pragma unroll
        for (int q = 0; q < 8; ++q) {
            int e = ebase + q * 32;
            bool up = ((e & k) == 0);
            u64 o = __shfl_xor_sync(0xFFFFFFFFu, K[q], j);
            bool upper = (e & j) != 0;              // == lane&j (j<=16)
            K[q] = (up != upper) ? u64min(K[q], o) : u64max(K[q], o);
        }
    }
}

__global__ void __launch_bounds__(NTHR, 1)
fused_kernel(const float* __restrict__ score_pred,
             const float* __restrict__ map2d,
             const float* __restrict__ offset_gt,
             const float* __restrict__ tmap,
             float* __restrict__ out)
{
    __shared__ u64 skeys[SORTN];                    // 32768 B
    __shared__ u16 rc[MM];                          // r | c<<8 (original order)
    __shared__ u16 smom[MM];                        // s | e<<8 (sorted order)
    __shared__ u32 maskw[NSEG], supw[NSEG], selw[NSEG];
    __shared__ u16 unsup_idx[MM];
    __shared__ u16 sel_idx[TOTALS];
    __shared__ u32 upref[NSEG + 1], spref[NSEG + 1];
    __shared__ u32 s_sel[KK];                       // r*64+c of final picks

    const int b    = blockIdx.x;
    const int tid  = threadIdx.x;
    const int lane = tid & 31;
    const int warp = tid >> 5;
    const int ebase = warp * 256 + lane;            // 8 elems: ebase + q*32

    // ---------------- Phase A: build keys (scatter by (r,c)) ----------------
    #pragma unroll
    for (int idx = tid; idx < SORTN; idx += NTHR) skeys[idx] = ~0ULL;
    __syncthreads();
    #pragma unroll
    for (int idx = tid; idx < NN * NN; idx += NTHR) {
        int r = idx >> 6, c = idx & 63;
        if (c >= r) {
            int e = (r * (129 - r)) / 2 + (c - r);
            float s = score_pred[b * (NN * NN) + idx];
            skeys[e] = ((u64)float_desc_key(s) << 32) | (u32)e;
            rc[e] = (u16)(r | (c << 8));
        }
    }
    __syncthreads();

    // ---------------- Phase B: bitonic sort, 8 elems/thread ----------------
    u64 K[8];
    #pragma unroll
    for (int q = 0; q < 8; ++q) K[q] = skeys[ebase + q * 32];

    // k = 2..256: fully warp-local (zero barriers)
    for (int k = 2; k <= 256; k <<= 1)
        reg_phase8(K, k, (k >> 1) > 128 ? 128 : (k >> 1), ebase);

    // ---- k = 512: single smem level j=256, then warp tail ----
    #pragma unroll
    for (int q = 0; q < 8; ++q) skeys[ebase + q * 32] = K[q];
    __syncthreads();
    #pragma unroll
    for (int i = 0; i < 4; ++i) {
        int t = tid + i * NTHR;
        int idx = ((t & ~255) << 1) | (t & 255);
        int p = idx | 256;
        bool up = ((idx & 512) == 0);
        u64 a = skeys[idx], c2 = skeys[p];
        if ((a > c2) == up) { skeys[idx] = c2; skeys[p] = a; }
    }
    __syncthreads();
    #pragma unroll
    for (int q = 0; q < 8; ++q) K[q] = skeys[ebase + q * 32];
    reg_phase8(K, 512, 128, ebase);

    // ---- k = 1024: fused2 (512,256), then warp tail ----
    #pragma unroll
    for (int q = 0; q < 8; ++q) skeys[ebase + q * 32] = K[q];
    __syncthreads();
    #pragma unroll
    for (int i = 0; i < 2; ++i) {
        int t = tid + i * NTHR;
        int base = ((t & ~255) << 2) | (t & 255);
        bool up = ((base & 1024) == 0);
        u64 a0 = skeys[base], a1 = skeys[base + 256];
        u64 a2 = skeys[base + 512], a3 = skeys[base + 768];
        cswap(a0, a2, up); cswap(a1, a3, up);       // j=512
        cswap(a0, a1, up); cswap(a2, a3, up);       // j=256
        skeys[base] = a0; skeys[base + 256] = a1;
        skeys[base + 512] = a2; skeys[base + 768] = a3;
    }
    __syncthreads();
    #pragma unroll
    for (int q = 0; q < 8; ++q) K[q] = skeys[ebase + q * 32];
    reg_phase8(K, 1024, 128, ebase);

    // ---- k = 2048: fused3 (1024,512,256), then warp tail ----
    #pragma unroll
    for (int q = 0; q < 8; ++q) skeys[ebase + q * 32] = K[q];
    __syncthreads();
    {
        int base = ((tid & ~255) << 3) | (tid & 255);
        bool up = ((base & 2048) == 0);
        u64 a[8];
        #pragma unroll
        for (int m = 0; m < 8; ++m) a[m] = skeys[base + m * 256];
        #pragma unroll
        for (int m = 0; m < 4; ++m) cswap(a[m], a[m + 4], up);      // j=1024
        cswap(a[0], a[2], up); cswap(a[1], a[3], up);               // j=512
        cswap(a[4], a[6], up); cswap(a[5], a[7], up);
        #pragma unroll
        for (int m = 0; m < 8; m += 2) cswap(a[m], a[m + 1], up);   // j=256
        #pragma unroll
        for (int m = 0; m < 8; ++m) skeys[base + m * 256] = a[m];
    }
    __syncthreads();
    #pragma unroll
    for (int q = 0; q < 8; ++q) K[q] = skeys[ebase + q * 32];
    reg_phase8(K, 2048, 128, ebase);

    // ---- k = 4096: fused4 (2048,1024,512,256), then warp tail ----
    #pragma unroll
    for (int q = 0; q < 8; ++q) skeys[ebase + q * 32] = K[q];
    __syncthreads();
    if (tid < 256) {                                // 16 elems per thread
        int base = ((tid & ~255) << 4) | (tid & 255);   // == tid (tid<256)
        u64 a[16];
        #pragma unroll
        for (int m = 0; m < 16; ++m) a[m] = skeys[base + m * 256];
        // k == SORTN: ascending everywhere (up = true)
        #pragma unroll
        for (int m = 0; m < 8; ++m) cswap(a[m], a[m + 8], true);    // j=2048
        #pragma unroll
        for (int h = 0; h < 16; h += 8)
            #pragma unroll
            for (int m = 0; m < 4; ++m) cswap(a[h + m], a[h + m + 4], true); // j=1024
        #pragma unroll
        for (int h = 0; h < 16; h += 4) {
            cswap(a[h], a[h + 2], true); cswap(a[h + 1], a[h + 3], true);    // j=512
        }
        #pragma unroll
        for (int m = 0; m < 16; m += 2) cswap(a[m], a[m + 1], true);         // j=256
        #pragma unroll
        for (int m = 0; m < 16; ++m) skeys[base + m * 256] = a[m];
    }
    __syncthreads();
    #pragma unroll
    for (int q = 0; q < 8; ++q) K[q] = skeys[ebase + q * 32];
    reg_phase8(K, 4096, 128, ebase);
    #pragma unroll
    for (int q = 0; q < 8; ++q) skeys[ebase + q * 32] = K[q];
    __syncthreads();

    // ---------------- Phase C: sorted moments (regs + smem), init state ----------------
    u32 mreg[5];                                    // this thread's smom values
    #pragma unroll
    for (int rd = 0; rd < 5; ++rd) {
        int i = tid + rd * NTHR;
        u32 v = 0;
        if (i < MM) {
            u32 e = (u32)skeys[i];
            u32 rcv = rc[e];
            int s = rcv & 0xFF;
            int en = (rcv >> 8) + 1;
            v = (u32)(s | (en << 8));
            smom[i] = (u16)v;
        }
        mreg[rd] = v;
    }
    if (tid < NSEG) { supw[tid] = 0u; selw[tid] = 0u; }
    __syncthreads();

    // ---------------- Phase D: greedy NMS (2 barriers/iter) ----------------
    {
        int i = 0, cnt = 0;
        while (cnt < TOPK) {
            // word-skip scan for next free index >= i (replicated, broadcast reads)
            {
                int s2 = i >> 5;
                u32 w = (~supw[s2]) & (0xFFFFFFFFu << (i & 31));
                while (w == 0 && s2 < NSEG - 1) { ++s2; w = ~supw[s2]; }
                i = w ? (s2 * 32 + __ffs(w) - 1) : MM;
            }
            if (i >= MM - 1) break;

            const int iseg = i >> 5;
            const u32 ibit = 1u << (i & 31);
            u32 mi = smom[i];                       // single broadcast LDS
            int si = mi & 0xFF, ei = mi >> 8;

            // ballot IoU masks from register moments (mask includes bit i)
            #pragma unroll
            for (int rd = 0; rd < 5; ++rd) {
                int e2 = tid + rd * NTHR;
                bool mk = false;
                if (e2 < MM) {
                    if (e2 == i) mk = true;
                    else if (e2 > i) {
                        u32 mmv = mreg[rd];
                        int s3 = mmv & 0xFF, e3 = mmv >> 8;
                        int inter = min(e3, ei) - max(s3, si);
                        if (inter > 0) {
                            int uni = max(e3, ei) - min(s3, si);
                            mk = (2 * inter > uni);      // == (iou > 0.5) exactly
                        }
                    }
                }
                u32 bal = __ballot_sync(0xFFFFFFFFu, mk);
                int seg = warp + rd * 16;
                if (lane == 0 && seg < NSEG) maskw[seg] = bal;
            }
            __syncthreads();

            // warp 0 does scan + suppression + selection in one in-warp pass
            if (warp == 0) {
                u32 full0 = maskw[lane];            // segs 0-31
                u32 full1 = maskw[lane + 32];       // segs 32-63
                u32 full2 = (lane == 0) ? maskw[64] : 0;
                u32 m0 = full0, m1 = full1, m2 = full2;
                if (lane == iseg)        m0 &= ~ibit;
                if (lane + 32 == iseg)   m1 &= ~ibit;
                if (lane == 0 && iseg == 64) m2 &= ~ibit;
                u32 v0 = __popc(m0), v1 = __popc(m1);
                u32 s0 = warp_incl_scan(v0, lane);
                u32 t0 = __shfl_sync(0xFFFFFFFFu, s0, 31);
                u32 s1 = warp_incl_scan(v1, lane) + t0;
                u32 nb0 = s0 - v0;
                u32 nb1 = s1 - v1;
                u32 nb2 = __shfl_sync(0xFFFFFFFFu, s1, 31);
                // suppression (mask includes pick bit)
                supw[lane]      |= full0;
                supw[lane + 32] |= full1;
                if (lane == 0) supw[64] |= full2;
                // selection: lowest (NEIGH - prefix) bits per segment + pick bit
                u32 add0 = low_bits(m0, NEIGH - (int)nb0);
                if (lane == iseg) add0 |= ibit;
                if (add0) selw[lane] |= add0;
                u32 add1 = low_bits(m1, NEIGH - (int)nb1);
                if (lane + 32 == iseg) add1 |= ibit;
                if (add1) selw[lane + 32] |= add1;
                if (lane == 0) {
                    u32 add2 = low_bits(m2, NEIGH - (int)nb2);
                    if (iseg == 64) add2 |= ibit;
                    if (add2) selw[64] |= add2;
                }
            }
            __syncthreads();
            ++i; ++cnt;
        }
        __syncthreads();   // uniform exit
    }

    // ---------------- Phase E: parallel compactions ----------------
    if (warp == 0) {       // unsup prefix
        u32 v0 = __popc(~supw[lane]);
        u32 v1 = __popc(~supw[lane + 32]);
        u32 v2 = (lane == 0) ? __popc(~supw[64]) : 0;
        u32 s0 = warp_incl_scan(v0, lane);
        u32 t0 = __shfl_sync(0xFFFFFFFFu, s0, 31);
        u32 s1 = warp_incl_scan(v1, lane) + t0;
        u32 t1 = __shfl_sync(0xFFFFFFFFu, s1, 31);
        upref[lane]      = s0 - v0;
        upref[lane + 32] = s1 - v1;
        if (lane == 0) { upref[64] = t1; upref[65] = t1 + v2; }
    }
    if (warp == 1) {       // sel prefix
        u32 v0 = __popc(selw[lane]);
        u32 v1 = __popc(selw[lane + 32]);
        u32 v2 = (lane == 0) ? __popc(selw[64]) : 0;
        u32 s0 = warp_incl_scan(v0, lane);
        u32 t0 = __shfl_sync(0xFFFFFFFFu, s0, 31);
        u32 s1 = warp_incl_scan(v1, lane) + t0;
        u32 t1 = __shfl_sync(0xFFFFFFFFu, s1, 31);
        spref[lane]      = s0 - v0;
        spref[lane + 32] = s1 - v1;
        if (lane == 0) { spref[64] = t1; spref[65] = t1 + v2; }
    }
    #pragma unroll
    for (int t = tid; t < MM; t += NTHR) unsup_idx[t] = (u16)(MM - 1);
    if (tid >= NTHR - TOTALS) sel_idx[tid - (NTHR - TOTALS)] = (u16)(MM - 1);
    __syncthreads();

    #pragma unroll
    for (int e2 = tid; e2 < MM; e2 += NTHR) {
        int s2 = e2 >> 5;
        u32 bit = 1u << (e2 & 31);
        u32 low = bit - 1u;
        u32 uw = ~supw[s2];
        if (uw & bit) unsup_idx[upref[s2] + __popc(uw & low)] = (u16)e2;
        u32 sw = selw[s2];
        if (sw & bit) sel_idx[spref[s2] + __popc(sw & low)] = (u16)e2;
    }
    __syncthreads();

    // ---------------- Phase F: final index assembly + small outputs ----------------
    if (tid < KK) {
        int n_unsup = (int)upref[NSEG];
        int n_sel   = (int)spref[NSEG];
        int pad     = TOTALS - n_sel;

        int idxS;
        if (tid < NEGK) {
            int t = n_unsup - 1 - tid;
            if (t < 0) t = 0;
            if (t > MM - 1) t = MM - 1;
            idxS = unsup_idx[t];
        } else {
            int p = tid - NEGK;
            if (p < pad) idxS = unsup_idx[p];
            else {
                int q = p - pad;
                if (q > TOTALS - 1) q = TOTALS - 1;
                idxS = sel_idx[q];
            }
        }
        u32 orig = (u32)skeys[idxS];         // order[idx_sorted]
        u32 rcv  = rc[orig];
        int r = rcv & 0xFF;
        int c = rcv >> 8;

        int gk = b * KK + tid;
        s_sel[tid] = (u32)(r * NN + c);

        out[SE_BASE + gk * 2 + 0] = (float)r;
        out[SE_BASE + gk * 2 + 1] = (float)(c + 1);

        size_t oidx = ((size_t)(b * NN + r) * NN + c) * 2;
        out[OFF_BASE + gk * 2 + 0] = offset_gt[oidx + 0];
        out[OFF_BASE + gk * 2 + 1] = offset_gt[oidx + 1];

        out[SC_BASE + gk] = tmap[(size_t)(b * NN + r) * NN + c];
    }
    __syncthreads();

    // ---------------- Phase G: fused feature gather (101 rows x 2KB) ----------------
    {
        const float4* __restrict__ src4 = (const float4*)map2d;
        float4* __restrict__ dst4 = (float4*)(out + FEAT_BASE);
        const size_t bbase = (size_t)b * (NN * NN) * (DD / 4);
        const size_t obase = (size_t)b * KK * (DD / 4);
        #pragma unroll 4
        for (int t = tid; t < KK * (DD / 4); t += NTHR) {
            int row = t >> 7;                 // /128 float4 per row
            int q   = t & 127;
            dst4[obase + (size_t)row * (DD / 4) + q] =
                src4[bbase + (size_t)s_sel[row] * (DD / 4) + q];
        }
    }
}

extern "C" void kernel_launch(void* const* d_in, const int* in_sizes, int n_in,
                              void* d_out, int out_size)
{
    const float* score_pred = (const float*)d_in[0];
    // d_in[1] = map2d_mask (deterministic triu — not needed)
    const float* map2d      = (const float*)d_in[2];
    const float* offset_gt  = (const float*)d_in[3];
    const float* tmap       = (const float*)d_in[4];
    float* out = (float*)d_out;

    fused_kernel<<<BATCH, NTHR>>>(score_pred, map2d, offset_gt, tmap, out);
}

// round 12
// speedup vs baseline: 2.1403x; 1.3774x over previous
#include <cuda_runtime.h>
#include <cuda_bf16.h>
#include <cstdint>

// Problem constants
#define BATCH   32
#define NN      64
#define DD      512
#define MM      2080          // N*(N+1)/2
#define SORTN   4096
#define NTHR    512
#define TOPK    5
#define NEIGH   16
#define NEGK    16
#define TOTALS  85            // TOPK*(NEIGH+1)
#define KK      101           // NEGK + TOTALS
#define NSEG    65            // 2080/32 exact

// Output layout (concatenated float32): feat, pred_s_e, offset, score
#define FEAT_BASE 0
#define SE_BASE   (BATCH*KK*DD)
#define OFF_BASE  (SE_BASE + BATCH*KK*2)
#define SC_BASE   (OFF_BASE + BATCH*KK*2)

typedef unsigned long long u64;
typedef unsigned int u32;
typedef unsigned short u16;

__device__ u64 g_keys[BATCH * SORTN];               // 1MB sort scratch

__device__ __forceinline__ u32 float_desc_key(float s) {
    u32 u = __float_as_uint(s);
    u32 k = (u & 0x80000000u) ? ~u : (u | 0x80000000u); // ascending map
    return ~k;                                          // descending
}

__device__ __forceinline__ u64 u64min(u64 a, u64 b) { return a < b ? a : b; }
__device__ __forceinline__ u64 u64max(u64 a, u64 b) { return a > b ? a : b; }

__device__ __forceinline__ void cswap(u64 &a, u64 &b, bool up) {
    if ((a > b) == up) { u64 t = a; a = b; b = t; }
}

__device__ __forceinline__ u32 warp_incl_scan(u32 v, int lane) {
    #pragma unroll
    for (int o = 1; o < 32; o <<= 1) {
        u32 t = __shfl_up_sync(0xFFFFFFFFu, v, o);
        if (lane >= o) v += t;
    }
    return v;
}

// lowest `rem` set bits of w (rem may exceed popc -> whole w)
__device__ __forceinline__ u32 low_bits(u32 w, int rem) {
    if (rem <= 0) return 0;
    if (__popc(w) <= rem) return w;
    u32 x = w;
    #pragma unroll
    for (int q = 0; q < NEIGH; ++q)
        if (q < rem) x &= (x - 1);
    return w ^ x;
}

// ---------------------------------------------------------------------------
// Kernel 1: per-quarter bitonic, stages k = 2..1024.
// 2 elems/thread; eg = GLOBAL element index (q*1024 + warp*64 + lane),
// K[0] at eg, K[1] at eg+32. Direction rule uses eg so the partial network
// is bit-identical to the full 4096 network's first phases.
// ---------------------------------------------------------------------------
__device__ __forceinline__ void reg_phase2(u64 K[2], int k, int jstart, int eg) {
    int j = jstart;
    if (j >= 32) {
        bool up = ((eg & k) == 0);                  // pair shares bits >= 6
        cswap(K[0], K[1], up);
        j = 16;
    }
    for (; j >= 1; j >>= 1) {
        #pragma unroll
        for (int q = 0; q < 2; ++q) {
            int e = eg + q * 32;
            bool up = ((e & k) == 0);
            u64 o = __shfl_xor_sync(0xFFFFFFFFu, K[q], j);
            bool upper = (e & j) != 0;              // == lane&j (j<=16)
            K[q] = (up != upper) ? u64min(K[q], o) : u64max(K[q], o);
        }
    }
}

__global__ void __launch_bounds__(NTHR, 2)
presort_kernel(const float* __restrict__ score_pred)
{
    __shared__ u64 sk[1024];                        // 8KB

    const int cta  = blockIdx.x;                    // b*4 + q
    const int b    = cta >> 2;
    const int qq   = cta & 3;
    const int tid  = threadIdx.x;
    const int lane = tid & 31;
    const int warp = tid >> 5;
    const int ebase = warp * 64 + lane;             // local, elems ebase, ebase+32
    const int eg    = qq * 1024 + ebase;            // global index

    // ---- build keys for this quarter ----
    sk[tid] = ~0ULL; sk[tid + 512] = ~0ULL;
    __syncthreads();
    const int elo = qq * 1024, ehi = elo + 1024;
    #pragma unroll
    for (int idx = tid; idx < NN * NN; idx += NTHR) {
        int r = idx >> 6, c = idx & 63;
        if (c >= r) {
            int e = (r * (129 - r)) / 2 + (c - r);
            if (e >= elo && e < ehi) {
                float s = score_pred[b * (NN * NN) + idx];
                sk[e - elo] = ((u64)float_desc_key(s) << 32) | (u32)e;
            }
        }
    }
    __syncthreads();

    u64 K[2];
    K[0] = sk[ebase]; K[1] = sk[ebase + 32];

    // k = 2..64: warp-local
    for (int k = 2; k <= 64; k <<= 1)
        reg_phase2(K, k, (k >> 1) > 32 ? 32 : (k >> 1), eg);

    // k = 128: smem level j=64, warp tail
    sk[ebase] = K[0]; sk[ebase + 32] = K[1];
    __syncthreads();
    {
        int i = ((tid & ~63) << 1) | (tid & 63);
        int p = i | 64;
        bool up = ((i & 128) == 0);
        u64 a = sk[i], c2 = sk[p];
        if ((a > c2) == up) { sk[i] = c2; sk[p] = a; }
    }
    __syncthreads();
    K[0] = sk[ebase]; K[1] = sk[ebase + 32];
    reg_phase2(K, 128, 32, eg);

    // k = 256: fused2 (128,64), warp tail
    sk[ebase] = K[0]; sk[ebase + 32] = K[1];
    __syncthreads();
    if (tid < 256) {
        int base = ((tid & ~63) << 2) | (tid & 63);
        bool up = ((base & 256) == 0);
        u64 a0 = sk[base], a1 = sk[base + 64], a2 = sk[base + 128], a3 = sk[base + 192];
        cswap(a0, a2, up); cswap(a1, a3, up);       // j=128
        cswap(a0, a1, up); cswap(a2, a3, up);       // j=64
        sk[base] = a0; sk[base + 64] = a1; sk[base + 128] = a2; sk[base + 192] = a3;
    }
    __syncthreads();
    K[0] = sk[ebase]; K[1] = sk[ebase + 32];
    reg_phase2(K, 256, 32, eg);

    // k = 512: fused3 (256,128,64), warp tail
    sk[ebase] = K[0]; sk[ebase + 32] = K[1];
    __syncthreads();
    if (tid < 128) {
        int base = ((tid & ~63) << 3) | (tid & 63);
        bool up = ((base & 512) == 0);
        u64 a[8];
        #pragma unroll
        for (int m = 0; m < 8; ++m) a[m] = sk[base + m * 64];
        #pragma unroll
        for (int m = 0; m < 4; ++m) cswap(a[m], a[m + 4], up);     // j=256
        cswap(a[0], a[2], up); cswap(a[1], a[3], up);              // j=128
        cswap(a[4], a[6], up); cswap(a[5], a[7], up);
        #pragma unroll
        for (int m = 0; m < 8; m += 2) cswap(a[m], a[m + 1], up);  // j=64
        #pragma unroll
        for (int m = 0; m < 8; ++m) sk[base + m * 64] = a[m];
    }
    __syncthreads();
    K[0] = sk[ebase]; K[1] = sk[ebase + 32];
    reg_phase2(K, 512, 32, eg);

    // k = 1024: direction depends on quarter parity (global bit 10)
    const bool qup = ((qq & 1) == 0);
    sk[ebase] = K[0]; sk[ebase + 32] = K[1];
    __syncthreads();
    if (tid < 256) {                                // fused2 (512,256)
        int base = tid;                             // ((tid&~255)<<2)|(tid&255), tid<256
        u64 a0 = sk[base], a1 = sk[base + 256], a2 = sk[base + 512], a3 = sk[base + 768];
        cswap(a0, a2, qup); cswap(a1, a3, qup);     // j=512
        cswap(a0, a1, qup); cswap(a2, a3, qup);     // j=256
        sk[base] = a0; sk[base + 256] = a1; sk[base + 512] = a2; sk[base + 768] = a3;
    }
    __syncthreads();
    if (tid < 256) {                                // fused2 (128,64)
        int base = ((tid & ~63) << 2) | (tid & 63);
        u64 a0 = sk[base], a1 = sk[base + 64], a2 = sk[base + 128], a3 = sk[base + 192];
        cswap(a0, a2, qup); cswap(a1, a3, qup);     // j=128
        cswap(a0, a1, qup); cswap(a2, a3, qup);     // j=64
        sk[base] = a0; sk[base + 64] = a1; sk[base + 128] = a2; sk[base + 192] = a3;
    }
    __syncthreads();
    K[0] = sk[ebase]; K[1] = sk[ebase + 32];
    reg_phase2(K, 1024, 32, eg);                    // (eg & 1024) == quarter parity

    // write run to scratch (coalesced per warp)
    g_keys[cta * 1024 + ebase]      = K[0];
    g_keys[cta * 1024 + ebase + 32] = K[1];
}

// ---------------------------------------------------------------------------
// Kernel 2: merge k=2048, k=4096 + NMS + compaction + outputs + gather.
// 8 elems/thread (warp spans 256): K[q] at ebase + q*32, ebase = warp*256+lane.
// ---------------------------------------------------------------------------
__device__ __forceinline__ void reg_phase8(u64 K[8], int k, int jstart, int ebase) {
    int j = jstart;
    if (j >= 128) {
        #pragma unroll
        for (int q = 0; q < 4; ++q) {
            bool up = (((ebase + q * 32) & k) == 0);
            cswap(K[q], K[q + 4], up);
        }
        j = 64;
    }
    if (j >= 64) {
        #pragma unroll
        for (int h = 0; h < 8; h += 4)
            #pragma unroll
            for (int q = 0; q < 2; ++q) {
                bool up = (((ebase + (h + q) * 32) & k) == 0);
                cswap(K[h + q], K[h + q + 2], up);
            }
        j = 32;
    }
    if (j >= 32) {
        #pragma unroll
        for (int q = 0; q < 8; q += 2) {
            bool up = (((ebase + q * 32) & k) == 0);
            cswap(K[q], K[q + 1], up);
        }
        j = 16;
    }
    for (; j >= 1; j >>= 1) {
        #pragma unroll
        for (int q = 0; q < 8; ++q) {
            int e = ebase + q * 32;
            bool up = ((e & k) == 0);
            u64 o = __shfl_xor_sync(0xFFFFFFFFu, K[q], j);
            bool upper = (e & j) != 0;
            K[q] = (up != upper) ? u64min(K[q], o) : u64max(K[q], o);
        }
    }
}

__global__ void __launch_bounds__(NTHR, 1)
merge_select_kernel(const float* __restrict__ map2d,
                    const float* __restrict__ offset_gt,
                    const float* __restrict__ tmap,
                    float* __restrict__ out)
{
    __shared__ u64 skeys[SORTN];                    // 32768 B
    __shared__ u16 rc[MM];
    __shared__ u16 smom[MM];
    __shared__ u32 maskw[NSEG], supw[NSEG], selw[NSEG];
    __shared__ u16 unsup_idx[MM];
    __shared__ u16 sel_idx[TOTALS];
    __shared__ u32 upref[NSEG + 1], spref[NSEG + 1];
    __shared__ u32 s_sel[KK];

    const int b    = blockIdx.x;
    const int tid  = threadIdx.x;
    const int lane = tid & 31;
    const int warp = tid >> 5;
    const int ebase = warp * 256 + lane;

    // ---- load sorted runs (coalesced) + build rc table ----
    #pragma unroll
    for (int i = tid; i < SORTN; i += NTHR)
        skeys[i] = g_keys[b * SORTN + i];
    #pragma unroll
    for (int idx = tid; idx < NN * NN; idx += NTHR) {
        int r = idx >> 6, c = idx & 63;
        if (c >= r) {
            int e = (r * (129 - r)) / 2 + (c - r);
            rc[e] = (u16)(r | (c << 8));
        }
    }
    __syncthreads();

    // ---- k = 2048: fused3 (1024,512,256), warp tail ----
    u64 K[8];
    {
        int base = ((tid & ~255) << 3) | (tid & 255);
        bool up = ((base & 2048) == 0);
        u64 a[8];
        #pragma unroll
        for (int m = 0; m < 8; ++m) a[m] = skeys[base + m * 256];
        #pragma unroll
        for (int m = 0; m < 4; ++m) cswap(a[m], a[m + 4], up);      // j=1024
        cswap(a[0], a[2], up); cswap(a[1], a[3], up);               // j=512
        cswap(a[4], a[6], up); cswap(a[5], a[7], up);
        #pragma unroll
        for (int m = 0; m < 8; m += 2) cswap(a[m], a[m + 1], up);   // j=256
        #pragma unroll
        for (int m = 0; m < 8; ++m) skeys[base + m * 256] = a[m];
    }
    __syncthreads();
    #pragma unroll
    for (int q = 0; q < 8; ++q) K[q] = skeys[ebase + q * 32];
    reg_phase8(K, 2048, 128, ebase);

    // ---- k = 4096: fused4 (2048,1024,512,256), warp tail ----
    #pragma unroll
    for (int q = 0; q < 8; ++q) skeys[ebase + q * 32] = K[q];
    __syncthreads();
    if (tid < 256) {
        int base = tid;
        u64 a[16];
        #pragma unroll
        for (int m = 0; m < 16; ++m) a[m] = skeys[base + m * 256];
        #pragma unroll
        for (int m = 0; m < 8; ++m) cswap(a[m], a[m + 8], true);    // j=2048
        #pragma unroll
        for (int h = 0; h < 16; h += 8)
            #pragma unroll
            for (int m = 0; m < 4; ++m) cswap(a[h + m], a[h + m + 4], true); // j=1024
        #pragma unroll
        for (int h = 0; h < 16; h += 4) {
            cswap(a[h], a[h + 2], true); cswap(a[h + 1], a[h + 3], true);    // j=512
        }
        #pragma unroll
        for (int m = 0; m < 16; m += 2) cswap(a[m], a[m + 1], true);         // j=256
        #pragma unroll
        for (int m = 0; m < 16; ++m) skeys[base + m * 256] = a[m];
    }
    __syncthreads();
    #pragma unroll
    for (int q = 0; q < 8; ++q) K[q] = skeys[ebase + q * 32];
    reg_phase8(K, 4096, 128, ebase);
    #pragma unroll
    for (int q = 0; q < 8; ++q) skeys[ebase + q * 32] = K[q];
    __syncthreads();

    // ---- sorted moments (regs + smem), init state ----
    u32 mreg[5];
    #pragma unroll
    for (int rd = 0; rd < 5; ++rd) {
        int i = tid + rd * NTHR;
        u32 v = 0;
        if (i < MM) {
            u32 e = (u32)skeys[i];
            u32 rcv = rc[e];
            int s = rcv & 0xFF;
            int en = (rcv >> 8) + 1;
            v = (u32)(s | (en << 8));
            smom[i] = (u16)v;
        }
        mreg[rd] = v;
    }
    if (tid < NSEG) { supw[tid] = 0u; selw[tid] = 0u; }
    __syncthreads();

    // ---- greedy NMS (2 barriers/iter) ----
    {
        int i = 0, cnt = 0;
        while (cnt < TOPK) {
            {
                int s2 = i >> 5;
                u32 w = (~supw[s2]) & (0xFFFFFFFFu << (i & 31));
                while (w == 0 && s2 < NSEG - 1) { ++s2; w = ~supw[s2]; }
                i = w ? (s2 * 32 + __ffs(w) - 1) : MM;
            }
            if (i >= MM - 1) break;

            const int iseg = i >> 5;
            const u32 ibit = 1u << (i & 31);
            u32 mi = smom[i];
            int si = mi & 0xFF, ei = mi >> 8;

            #pragma unroll
            for (int rd = 0; rd < 5; ++rd) {
                int e2 = tid + rd * NTHR;
                bool mk = false;
                if (e2 < MM) {
                    if (e2 == i) mk = true;
                    else if (e2 > i) {
                        u32 mmv = mreg[rd];
                        int s3 = mmv & 0xFF, e3 = mmv >> 8;
                        int inter = min(e3, ei) - max(s3, si);
                        if (inter > 0) {
                            int uni = max(e3, ei) - min(s3, si);
                            mk = (2 * inter > uni);
                        }
                    }
                }
                u32 bal = __ballot_sync(0xFFFFFFFFu, mk);
                int seg = warp + rd * 16;
                if (lane == 0 && seg < NSEG) maskw[seg] = bal;
            }
            __syncthreads();

            if (warp == 0) {
                u32 full0 = maskw[lane];
                u32 full1 = maskw[lane + 32];
                u32 full2 = (lane == 0) ? maskw[64] : 0;
                u32 m0 = full0, m1 = full1, m2 = full2;
                if (lane == iseg)        m0 &= ~ibit;
                if (lane + 32 == iseg)   m1 &= ~ibit;
                if (lane == 0 && iseg == 64) m2 &= ~ibit;
                u32 v0 = __popc(m0), v1 = __popc(m1);
                u32 s0 = warp_incl_scan(v0, lane);
                u32 t0 = __shfl_sync(0xFFFFFFFFu, s0, 31);
                u32 s1 = warp_incl_scan(v1, lane) + t0;
                u32 nb0 = s0 - v0;
                u32 nb1 = s1 - v1;
                u32 nb2 = __shfl_sync(0xFFFFFFFFu, s1, 31);
                supw[lane]      |= full0;
                supw[lane + 32] |= full1;
                if (lane == 0) supw[64] |= full2;
                u32 add0 = low_bits(m0, NEIGH - (int)nb0);
                if (lane == iseg) add0 |= ibit;
                if (add0) selw[lane] |= add0;
                u32 add1 = low_bits(m1, NEIGH - (int)nb1);
                if (lane + 32 == iseg) add1 |= ibit;
                if (add1) selw[lane + 32] |= add1;
                if (lane == 0) {
                    u32 add2 = low_bits(m2, NEIGH - (int)nb2);
                    if (iseg == 64) add2 |= ibit;
                    if (add2) selw[64] |= add2;
                }
            }
            __syncthreads();
            ++i; ++cnt;
        }
        __syncthreads();
    }

    // ---- parallel compactions ----
    if (warp == 0) {
        u32 v0 = __popc(~supw[lane]);
        u32 v1 = __popc(~supw[lane + 32]);
        u32 v2 = (lane == 0) ? __popc(~supw[64]) : 0;
        u32 s0 = warp_incl_scan(v0, lane);
        u32 t0 = __shfl_sync(0xFFFFFFFFu, s0, 31);
        u32 s1 = warp_incl_scan(v1, lane) + t0;
        u32 t1 = __shfl_sync(0xFFFFFFFFu, s1, 31);
        upref[lane]      = s0 - v0;
        upref[lane + 32] = s1 - v1;
        if (lane == 0) { upref[64] = t1; upref[65] = t1 + v2; }
    }
    if (warp == 1) {
        u32 v0 = __popc(selw[lane]);
        u32 v1 = __popc(selw[lane + 32]);
        u32 v2 = (lane == 0) ? __popc(selw[64]) : 0;
        u32 s0 = warp_incl_scan(v0, lane);
        u32 t0 = __shfl_sync(0xFFFFFFFFu, s0, 31);
        u32 s1 = warp_incl_scan(v1, lane) + t0;
        u32 t1 = __shfl_sync(0xFFFFFFFFu, s1, 31);
        spref[lane]      = s0 - v0;
        spref[lane + 32] = s1 - v1;
        if (lane == 0) { spref[64] = t1; spref[65] = t1 + v2; }
    }
    #pragma unroll
    for (int t = tid; t < MM; t += NTHR) unsup_idx[t] = (u16)(MM - 1);
    if (tid >= NTHR - TOTALS) sel_idx[tid - (NTHR - TOTALS)] = (u16)(MM - 1);
    __syncthreads();

    #pragma unroll
    for (int e2 = tid; e2 < MM; e2 += NTHR) {
        int s2 = e2 >> 5;
        u32 bit = 1u << (e2 & 31);
        u32 low = bit - 1u;
        u32 uw = ~supw[s2];
        if (uw & bit) unsup_idx[upref[s2] + __popc(uw & low)] = (u16)e2;
        u32 sw = selw[s2];
        if (sw & bit) sel_idx[spref[s2] + __popc(sw & low)] = (u16)e2;
    }
    __syncthreads();

    // ---- final index assembly + small outputs ----
    if (tid < KK) {
        int n_unsup = (int)upref[NSEG];
        int n_sel   = (int)spref[NSEG];
        int pad     = TOTALS - n_sel;

        int idxS;
        if (tid < NEGK) {
            int t = n_unsup - 1 - tid;
            if (t < 0) t = 0;
            if (t > MM - 1) t = MM - 1;
            idxS = unsup_idx[t];
        } else {
            int p = tid - NEGK;
            if (p < pad) idxS = unsup_idx[p];
            else {
                int q = p - pad;
                if (q > TOTALS - 1) q = TOTALS - 1;
                idxS = sel_idx[q];
            }
        }
        u32 orig = (u32)skeys[idxS];
        u32 rcv  = rc[orig];
        int r = rcv & 0xFF;
        int c = rcv >> 8;

        int gk = b * KK + tid;
        s_sel[tid] = (u32)(r * NN + c);

        out[SE_BASE + gk * 2 + 0] = (float)r;
        out[SE_BASE + gk * 2 + 1] = (float)(c + 1);

        size_t oidx = ((size_t)(b * NN + r) * NN + c) * 2;
        out[OFF_BASE + gk * 2 + 0] = offset_gt[oidx + 0];
        out[OFF_BASE + gk * 2 + 1] = offset_gt[oidx + 1];

        out[SC_BASE + gk] = tmap[(size_t)(b * NN + r) * NN + c];
    }
    __syncthreads();

    // ---- fused feature gather (101 rows x 2KB) ----
    {
        const float4* __restrict__ src4 = (const float4*)map2d;
        float4* __restrict__ dst4 = (float4*)(out + FEAT_BASE);
        const size_t bbase = (size_t)b * (NN * NN) * (DD / 4);
        const size_t obase = (size_t)b * KK * (DD / 4);
        #pragma unroll 4
        for (int t = tid; t < KK * (DD / 4); t += NTHR) {
            int row = t >> 7;
            int q   = t & 127;
            dst4[obase + (size_t)row * (DD / 4) + q] =
                src4[bbase + (size_t)s_sel[row] * (DD / 4) + q];
        }
    }
}

extern "C" void kernel_launch(void* const* d_in, const int* in_sizes, int n_in,
                              void* d_out, int out_size)
{
    const float* score_pred = (const float*)d_in[0];
    // d_in[1] = map2d_mask (deterministic triu — not needed)
    const float* map2d      = (const float*)d_in[2];
    const float* offset_gt  = (const float*)d_in[3];
    const float* tmap       = (const float*)d_in[4];
    float* out = (float*)d_out;

    presort_kernel<<<BATCH * 4, NTHR>>>(score_pred);
    merge_select_kernel<<<BATCH, NTHR>>>(map2d, offset_gt, tmap, out);
}